// round 7
// baseline (speedup 1.0000x reference)
#include <cuda_runtime.h>
#include <cuda_bf16.h>
#include <cstdint>

// Hamming1Layer fused kernel, v5 (SIMT; tcgen05 not available: harness PTX targets sm_103).
// y[b,c,l] = (w_self*x[b,c,l] + sum_k w_bits[k]*x[b,c,l^(1<<k)]) / 15
// out[b,o,l] = sum_c mix_w[o,c]*y[b,c,l] + mix_b[o]
// B=32, C_IN=32, C_OUT=64, L=16384, N_BITS=14.
//
// v5 vs v4 (118.9us, latency-bound: occ 22.7%, issue 29%, nothing saturated):
//  - __launch_bounds__(256,3): reg cap 85, 3 blocks/SM -> 24 warps (was 16)
//  - TILE_L=256, 2048 blocks (v2 wave structure), SMEM 64.5 KiB/block
//  - mix tile 4o x 4pair (32 acc regs) x 2 phases, broadcast-merged lanes
//  - gather keeps quad trick (bits 0,1 free) + bf16 in-tile bits 2..7,
//    bits 8..13 from L2-hot global

#define NBITS   14
#define LPOW    16384
#define CIN     32
#define COUT    64
#define TILE_L  256
#define QUADS   (TILE_L / 4)      // 64
#define TPB     256

// ---- smem map (bytes) ----
#define SMEM_XB    0                             // bf16 [CIN][TILE_L]      = 16 KiB
#define SMEM_Y     (CIN * TILE_L * 2)            // f32  [CIN][TILE_L]      = 32 KiB
#define SMEM_W     (SMEM_Y + CIN * TILE_L * 4)   // u64  [CIN][COUT] (w,w)  = 16 KiB
#define SMEM_B     (SMEM_W + CIN * COUT * 8)     // u64  [COUT]  (b,b)      = 512 B
#define SMEM_TOTAL (SMEM_B + COUT * 8)           // 64.5 KiB -> 3 blocks/SM

__device__ __forceinline__ uint64_t pack2(float lo, float hi) {
    uint64_t r;
    asm("mov.b64 %0, {%1, %2};" : "=l"(r) : "f"(lo), "f"(hi));
    return r;
}
__device__ __forceinline__ void unpack2(uint64_t v, float& lo, float& hi) {
    asm("mov.b64 {%0, %1}, %2;" : "=f"(lo), "=f"(hi) : "l"(v));
}
__device__ __forceinline__ uint64_t fma2(uint64_t a, uint64_t b, uint64_t c) {
    uint64_t d;
    asm("fma.rn.f32x2 %0, %1, %2, %3;" : "=l"(d) : "l"(a), "l"(b), "l"(c));
    return d;
}
__device__ __forceinline__ uint64_t mul2(uint64_t a, uint64_t b) {
    uint64_t d;
    asm("mul.rn.f32x2 %0, %1, %2;" : "=l"(d) : "l"(a), "l"(b));
    return d;
}
// bf16x2 word -> f32x2 pair (elem0 -> lo, elem1 -> hi)
__device__ __forceinline__ uint64_t bfp_to_f32x2(uint32_t v) {
    uint32_t lo = v << 16;
    uint32_t hi = v & 0xFFFF0000u;
    uint64_t r;
    asm("mov.b64 %0, {%1, %2};" : "=l"(r) : "r"(lo), "r"(hi));
    return r;
}
// two f32 -> bf16x2 word (a -> lo, b -> hi)
__device__ __forceinline__ uint32_t f2_to_bfp(float a, float b) {
    uint32_t r;
    asm("cvt.rn.bf16x2.f32 %0, %1, %2;" : "=r"(r) : "f"(b), "f"(a));
    return r;
}

extern __shared__ unsigned char smem_raw[];

__global__ __launch_bounds__(TPB, 3)
void hamming_kernel(const float* __restrict__ x,
                    const float* __restrict__ w_self,
                    const float* __restrict__ w_bits,
                    const float* __restrict__ mix_w,
                    const float* __restrict__ mix_b,
                    float* __restrict__ out)
{
    uint32_t*  sh_xb = (uint32_t*)(smem_raw + SMEM_XB);   // bf16x2 words [c][TILE_L/2]
    float*     sh_y  = (float*)   (smem_raw + SMEM_Y);    // [c][TILE_L]
    uint64_t*  sh_w  = (uint64_t*)(smem_raw + SMEM_W);    // [c][COUT] packed (w,w)
    uint64_t*  sh_b  = (uint64_t*)(smem_raw + SMEM_B);    // [COUT]  packed (b,b)

    const int tid   = threadIdx.x;
    const int tile  = blockIdx.x;            // 0..63
    const int b     = blockIdx.y;            // 0..31
    const int lbase = tile * TILE_L;

    // ---- stage mix weights (1/15 folded, pre-packed (w,w)) + bias ----
    const float inv15 = 1.0f / 15.0f;
    for (int e = tid; e < CIN * COUT; e += TPB) {
        int o = e & 63, c = e >> 6;
        float w = mix_w[o * CIN + c] * inv15;
        sh_w[c * COUT + o] = pack2(w, w);
    }
    if (tid < COUT) {
        float v = mix_b[tid];
        sh_b[tid] = pack2(v, v);
    }

    // ---- stage bf16 x tile: x[b, :, lbase:lbase+256] ----
    const float4* xg4 = (const float4*)(x + (size_t)b * CIN * LPOW);
    #pragma unroll
    for (int i = 0; i < (CIN * TILE_L / 4) / TPB; ++i) {    // 8 iters
        int j  = i * TPB + tid;          // float4 slot
        int c  = j >> 6;                 // TILE_L/4 = 64 per c
        int lw = j & 63;
        float4 f = xg4[(size_t)c * (LPOW / 4) + (lbase >> 2) + lw];
        uint2 p;
        p.x = f2_to_bfp(f.x, f.y);
        p.y = f2_to_bfp(f.z, f.w);
        *(uint2*)(sh_xb + c * (TILE_L / 2) + lw * 2) = p;
    }

    // per-thread packed gather weights
    const float ws = *w_self;
    const uint64_t ws2 = pack2(ws, ws);
    uint64_t wb2[NBITS];
    #pragma unroll
    for (int k = 0; k < NBITS; ++k) {
        float v = w_bits[k];
        wb2[k] = pack2(v, v);
    }
    __syncthreads();

    // ================= gather: item = (c, quad of 4 l) =================
    // lanes cover consecutive quads of the same c -> coalesced everywhere.
    const float* xb = x + (size_t)b * CIN * LPOW;
    #pragma unroll 2
    for (int it = 0; it < (CIN * QUADS) / TPB; ++it) {      // 8 iters
        int idx = it * TPB + tid;
        int c   = idx >> 6;              // QUADS=64 per c
        int q   = idx & 63;

        const float4*   xc4 = (const float4*)(xb + (size_t)c * LPOW);
        const uint32_t* row = sh_xb + c * (TILE_L / 2);

        // self quad (f32, L1-hot from staging)
        float4 s = xc4[(lbase >> 2) + q];

        // self + bit0 (in-pair swap) + bit1 (pair swap) from registers
        uint64_t s01 = pack2(s.x, s.y), s23 = pack2(s.z, s.w);
        uint64_t a01 = mul2(ws2, s01);
        uint64_t a23 = mul2(ws2, s23);
        a01 = fma2(wb2[0], pack2(s.y, s.x), a01);
        a23 = fma2(wb2[0], pack2(s.w, s.z), a23);
        a01 = fma2(wb2[1], s23, a01);
        a23 = fma2(wb2[1], s01, a23);

        // bits 2..7: bf16 quads from SMEM tile
        #pragma unroll
        for (int k = 2; k <= 7; ++k) {
            int qn = q ^ (1 << (k - 2));            // neighbor quad index
            uint2 n = *(const uint2*)(row + qn * 2);
            a01 = fma2(wb2[k], bfp_to_f32x2(n.x), a01);
            a23 = fma2(wb2[k], bfp_to_f32x2(n.y), a23);
        }

        // bits 8..13: f32 quads from global (L2-hot: batch slice = 2 MiB)
        #pragma unroll
        for (int k = 8; k < NBITS; ++k) {
            float4 g = xc4[((lbase ^ (1 << k)) >> 2) + q];
            a01 = fma2(wb2[k], pack2(g.x, g.y), a01);
            a23 = fma2(wb2[k], pack2(g.z, g.w), a23);
        }

        // store y quad (f32)
        float y0, y1, y2, y3;
        unpack2(a01, y0, y1);
        unpack2(a23, y2, y3);
        *(float4*)(sh_y + c * TILE_L + q * 4) = make_float4(y0, y1, y2, y3);
    }
    __syncthreads();

    // ================= mix: 4o x 4pair register tile, 2 phases ============
    // og = tid>>4 in [0,16) -> o rows [4og, 4og+4); pg = tid&15 -> pairs.
    // Within a warp: og takes 2 values (broadcast-merged w loads),
    // pg spans 0..15 twice (sequential y loads, lanes 16-31 merge).
    const int og = tid >> 4;
    const int pg = tid & 15;
    const int ob = og * 4;

    uint64_t* outp = (uint64_t*)out + (size_t)b * COUT * (LPOW / 2) + (lbase >> 1);

    #pragma unroll
    for (int ph = 0; ph < 2; ++ph) {
        const int pbase = ph * 64 + pg * 4;          // first pair of this thread
        const int ebase = 2 * pbase;                 // f32 element offset

        uint64_t acc[4][4];
        #pragma unroll
        for (int i = 0; i < 4; ++i) {
            uint64_t bias = sh_b[ob + i];
            #pragma unroll
            for (int j = 0; j < 4; ++j) acc[i][j] = bias;
        }

        #pragma unroll 4
        for (int c = 0; c < CIN; ++c) {
            // w: 4 packed u64 = 2x LDS.128, broadcast within half-warp
            const uint64_t* wr = sh_w + c * COUT + ob;
            uint64_t w0 = wr[0], w1 = wr[1], w2 = wr[2], w3 = wr[3];

            // y: 4 pairs = 8 f32 = 2x LDS.128, sequential across pg
            const float4* yr = (const float4*)(sh_y + c * TILE_L + ebase);
            float4 yA = yr[0], yB = yr[1];
            uint64_t y0 = pack2(yA.x, yA.y), y1 = pack2(yA.z, yA.w);
            uint64_t y2 = pack2(yB.x, yB.y), y3 = pack2(yB.z, yB.w);

            acc[0][0] = fma2(w0, y0, acc[0][0]); acc[0][1] = fma2(w0, y1, acc[0][1]);
            acc[0][2] = fma2(w0, y2, acc[0][2]); acc[0][3] = fma2(w0, y3, acc[0][3]);
            acc[1][0] = fma2(w1, y0, acc[1][0]); acc[1][1] = fma2(w1, y1, acc[1][1]);
            acc[1][2] = fma2(w1, y2, acc[1][2]); acc[1][3] = fma2(w1, y3, acc[1][3]);
            acc[2][0] = fma2(w2, y0, acc[2][0]); acc[2][1] = fma2(w2, y1, acc[2][1]);
            acc[2][2] = fma2(w2, y2, acc[2][2]); acc[2][3] = fma2(w2, y3, acc[2][3]);
            acc[3][0] = fma2(w3, y0, acc[3][0]); acc[3][1] = fma2(w3, y1, acc[3][1]);
            acc[3][2] = fma2(w3, y2, acc[3][2]); acc[3][3] = fma2(w3, y3, acc[3][3]);
        }

        #pragma unroll
        for (int i = 0; i < 4; ++i) {
            uint64_t* orow = outp + (size_t)(ob + i) * (LPOW / 2) + pbase;
            #pragma unroll
            for (int j = 0; j < 4; ++j)
                orow[j] = acc[i][j];
        }
    }
}

extern "C" void kernel_launch(void* const* d_in, const int* in_sizes, int n_in,
                              void* d_out, int out_size)
{
    const float* x      = (const float*)d_in[0];
    const float* w_self = (const float*)d_in[1];
    const float* w_bits = (const float*)d_in[2];
    const float* mix_w  = (const float*)d_in[3];
    const float* mix_b  = (const float*)d_in[4];
    float* out = (float*)d_out;

    cudaFuncSetAttribute(hamming_kernel,
                         cudaFuncAttributeMaxDynamicSharedMemorySize, SMEM_TOTAL);

    dim3 grid(LPOW / TILE_L, 32, 1);   // (64 tiles, 32 batches) = 2048 blocks
    hamming_kernel<<<grid, TPB, SMEM_TOTAL>>>(x, w_self, w_bits, mix_w, mix_b, out);
}

// round 8
// speedup vs baseline: 1.5191x; 1.5191x over previous
#include <cuda_runtime.h>
#include <cuda_bf16.h>
#include <cstdint>

// Hamming1Layer fused kernel, v6: warp-specialized producer/consumer pipeline.
// y[b,c,l] = (w_self*x[b,c,l] + sum_k w_bits[k]*x[b,c,l^(1<<k)]) / 15
// out[b,o,l] = sum_c mix_w[o,c]*y[b,c,l] + mix_b[o]
// B=32, C_IN=32, C_OUT=64, L=16384, N_BITS=14.
//
// v6 vs v4/v5 (113-144us, phase-serialized latency-bound):
//  - warps 0-3 gather (LSU/latency), warps 4-7 mix GEMM (fma pipe),
//    double-buffered 128-l y chunks -> gather latency hidden behind mix compute
//  - mix y-loads re-strided (pairs pg+16j): conflict-free 128B LDS wavefronts
//    (v4/v5 pg*32B stride was a 4-way bank conflict)
//  - w pre-packed (w,w) u64 -> LDS.128 broadcast loads
//  - gather keeps v4 quad trick: bits 0,1 register permutes; bits 2..8 bf16
//    in-tile; bits 9..13 f32 from L2-hot global; self f32 (precision)

#define NBITS   14
#define LPOW    16384
#define CIN     32
#define COUT    64
#define TILE_L  512
#define CHUNK_L 128
#define NCHUNK  (TILE_L / CHUNK_L)     // 4
#define CQUADS  (CHUNK_L / 4)          // 32
#define CPAIRS  (CHUNK_L / 2)          // 64
#define TPB     256

// ---- smem map (bytes) ----
#define SMEM_XB    0                               // bf16 [CIN][TILE_L]        = 32 KiB
#define SMEM_YB    32768                           // f32  [2][CIN][CHUNK_L]    = 32 KiB
#define SMEM_W     65536                           // u64  [CIN][COUT] (w,w)    = 16 KiB
#define SMEM_B     81920                           // u64  [COUT] (b,b)         = 512 B
#define SMEM_TOTAL 82432                           // ~80.5 KiB -> 2 blocks/SM

__device__ __forceinline__ uint64_t pack2(float lo, float hi) {
    uint64_t r;
    asm("mov.b64 %0, {%1, %2};" : "=l"(r) : "f"(lo), "f"(hi));
    return r;
}
__device__ __forceinline__ void unpack2(uint64_t v, float& lo, float& hi) {
    asm("mov.b64 {%0, %1}, %2;" : "=f"(lo), "=f"(hi) : "l"(v));
}
__device__ __forceinline__ uint64_t fma2(uint64_t a, uint64_t b, uint64_t c) {
    uint64_t d;
    asm("fma.rn.f32x2 %0, %1, %2, %3;" : "=l"(d) : "l"(a), "l"(b), "l"(c));
    return d;
}
__device__ __forceinline__ uint64_t mul2(uint64_t a, uint64_t b) {
    uint64_t d;
    asm("mul.rn.f32x2 %0, %1, %2;" : "=l"(d) : "l"(a), "l"(b));
    return d;
}
__device__ __forceinline__ uint64_t add2(uint64_t a, uint64_t b) {
    uint64_t d;
    asm("add.rn.f32x2 %0, %1, %2;" : "=l"(d) : "l"(a), "l"(b));
    return d;
}
// bf16x2 word -> f32x2 pair (elem0 -> lo, elem1 -> hi)
__device__ __forceinline__ uint64_t bfp_to_f32x2(uint32_t v) {
    uint32_t lo = v << 16;
    uint32_t hi = v & 0xFFFF0000u;
    uint64_t r;
    asm("mov.b64 %0, {%1, %2};" : "=l"(r) : "r"(lo), "r"(hi));
    return r;
}
// two f32 -> bf16x2 word (a -> lo, b -> hi)
__device__ __forceinline__ uint32_t f2_to_bfp(float a, float b) {
    uint32_t r;
    asm("cvt.rn.bf16x2.f32 %0, %1, %2;" : "=r"(r) : "f"(b), "f"(a));
    return r;
}

extern __shared__ unsigned char smem_raw[];

// ---------- consumer: mix one 128-l chunk (warps 4-7, tl = tid-128) ----------
__device__ __forceinline__ void mix_chunk(const uint64_t* __restrict__ ybuf,   // [CIN][CPAIRS] u64 pairs
                                          const uint64_t* __restrict__ sh_w,   // [CIN][COUT] packed
                                          const uint64_t* __restrict__ sh_b,
                                          uint64_t* __restrict__ outp,         // + pair base of chunk
                                          int tl)
{
    const int og = tl >> 4;           // 0..7 -> o rows [8og, 8og+8)
    const int pg = tl & 15;           // pairs pg + 16j, j=0..3
    const int ob = og * 8;

    uint64_t acc[8][4];
    #pragma unroll
    for (int i = 0; i < 8; ++i) {
        uint64_t bias = sh_b[ob + i];
        #pragma unroll
        for (int j = 0; j < 4; ++j) acc[i][j] = bias;
    }

    #pragma unroll 4
    for (int c = 0; c < CIN; ++c) {
        // w: 8 packed u64 via 4 LDS.128 (broadcast within 16-lane group)
        const ulonglong2* wr = (const ulonglong2*)(sh_w + c * COUT + ob);
        ulonglong2 wA = wr[0], wB = wr[1], wC = wr[2], wD = wr[3];

        // y: 4 pairs at stride 16 -> 4 conflict-free LDS.64 (128B wavefronts)
        const uint64_t* yc = ybuf + c * CPAIRS + pg;
        uint64_t y0 = yc[0], y1 = yc[16], y2 = yc[32], y3 = yc[48];

        acc[0][0] = fma2(wA.x, y0, acc[0][0]); acc[0][1] = fma2(wA.x, y1, acc[0][1]);
        acc[0][2] = fma2(wA.x, y2, acc[0][2]); acc[0][3] = fma2(wA.x, y3, acc[0][3]);
        acc[1][0] = fma2(wA.y, y0, acc[1][0]); acc[1][1] = fma2(wA.y, y1, acc[1][1]);
        acc[1][2] = fma2(wA.y, y2, acc[1][2]); acc[1][3] = fma2(wA.y, y3, acc[1][3]);
        acc[2][0] = fma2(wB.x, y0, acc[2][0]); acc[2][1] = fma2(wB.x, y1, acc[2][1]);
        acc[2][2] = fma2(wB.x, y2, acc[2][2]); acc[2][3] = fma2(wB.x, y3, acc[2][3]);
        acc[3][0] = fma2(wB.y, y0, acc[3][0]); acc[3][1] = fma2(wB.y, y1, acc[3][1]);
        acc[3][2] = fma2(wB.y, y2, acc[3][2]); acc[3][3] = fma2(wB.y, y3, acc[3][3]);
        acc[4][0] = fma2(wC.x, y0, acc[4][0]); acc[4][1] = fma2(wC.x, y1, acc[4][1]);
        acc[4][2] = fma2(wC.x, y2, acc[4][2]); acc[4][3] = fma2(wC.x, y3, acc[4][3]);
        acc[5][0] = fma2(wC.y, y0, acc[5][0]); acc[5][1] = fma2(wC.y, y1, acc[5][1]);
        acc[5][2] = fma2(wC.y, y2, acc[5][2]); acc[5][3] = fma2(wC.y, y3, acc[5][3]);
        acc[6][0] = fma2(wD.x, y0, acc[6][0]); acc[6][1] = fma2(wD.x, y1, acc[6][1]);
        acc[6][2] = fma2(wD.x, y2, acc[6][2]); acc[6][3] = fma2(wD.x, y3, acc[6][3]);
        acc[7][0] = fma2(wD.y, y0, acc[7][0]); acc[7][1] = fma2(wD.y, y1, acc[7][1]);
        acc[7][2] = fma2(wD.y, y2, acc[7][2]); acc[7][3] = fma2(wD.y, y3, acc[7][3]);
    }

    #pragma unroll
    for (int i = 0; i < 8; ++i) {
        uint64_t* orow = outp + (size_t)(ob + i) * (LPOW / 2) + pg;
        orow[0]  = acc[i][0];
        orow[16] = acc[i][1];
        orow[32] = acc[i][2];
        orow[48] = acc[i][3];
    }
}

__global__ __launch_bounds__(TPB, 2)
void hamming_kernel(const float* __restrict__ x,
                    const float* __restrict__ w_self,
                    const float* __restrict__ w_bits,
                    const float* __restrict__ mix_w,
                    const float* __restrict__ mix_b,
                    float* __restrict__ out)
{
    uint32_t*  sh_xb = (uint32_t*)(smem_raw + SMEM_XB);   // bf16x2 words [c][TILE_L/2]
    float*     sh_y  = (float*)   (smem_raw + SMEM_YB);   // [2][c][CHUNK_L]
    uint64_t*  sh_w  = (uint64_t*)(smem_raw + SMEM_W);
    uint64_t*  sh_b  = (uint64_t*)(smem_raw + SMEM_B);

    const int tid   = threadIdx.x;
    const int tile  = blockIdx.x;            // 0..31
    const int b     = blockIdx.y;            // 0..31
    const int lbase = tile * TILE_L;

    // ---- cooperative staging (all 256 threads) ----
    const float inv15 = 1.0f / 15.0f;
    for (int e = tid; e < CIN * COUT; e += TPB) {
        int o = e & 63, c = e >> 6;
        float w = mix_w[o * CIN + c] * inv15;
        sh_w[c * COUT + o] = pack2(w, w);
    }
    if (tid < COUT) {
        float v = mix_b[tid];
        sh_b[tid] = pack2(v, v);
    }

    const float4* xg4 = (const float4*)(x + (size_t)b * CIN * LPOW);
    #pragma unroll
    for (int i = 0; i < (CIN * TILE_L / 4) / TPB; ++i) {    // 16 iters
        int j  = i * TPB + tid;
        int c  = j >> 7;                 // 128 float4 per c
        int lw = j & 127;
        float4 f = xg4[(size_t)c * (LPOW / 4) + (lbase >> 2) + lw];
        uint2 p;
        p.x = f2_to_bfp(f.x, f.y);
        p.y = f2_to_bfp(f.z, f.w);
        *(uint2*)(sh_xb + c * (TILE_L / 2) + lw * 2) = p;
    }
    __syncthreads();

    const bool producer = (tid < 128);

    if (producer) {
        // ---------------- producer: gather chunks 0..3 ----------------
        const float ws = *w_self;
        const uint64_t ws2 = pack2(ws, ws);
        uint64_t wb2[NBITS];
        #pragma unroll
        for (int k = 0; k < NBITS; ++k) {
            float v = w_bits[k];
            wb2[k] = pack2(v, v);
        }
        const float* xb = x + (size_t)b * CIN * LPOW;

        for (int ck = 0; ck < NCHUNK; ++ck) {
            float* ybuf = sh_y + (ck & 1) * CIN * CHUNK_L;
            // items: 32c x 32 quads / 128 threads = 8 iters; warp = one c per iter
            #pragma unroll 2
            for (int it = 0; it < (CIN * CQUADS) / 128; ++it) {
                int idx = it * 128 + tid;
                int c   = idx >> 5;              // 0..31
                int ql  = idx & 31;              // quad in chunk
                int qg  = ck * CQUADS + ql;      // quad in tile [0,128)

                const float4*   xc4 = (const float4*)(xb + (size_t)c * LPOW);
                const uint32_t* row = sh_xb + c * (TILE_L / 2);

                // issue all global loads first (self f32 + 5 remote)
                float4 s  = xc4[(lbase >> 2) + qg];
                float4 g9  = xc4[((lbase ^ (1 <<  9)) >> 2) + qg];
                float4 g10 = xc4[((lbase ^ (1 << 10)) >> 2) + qg];
                float4 g11 = xc4[((lbase ^ (1 << 11)) >> 2) + qg];
                float4 g12 = xc4[((lbase ^ (1 << 12)) >> 2) + qg];
                float4 g13 = xc4[((lbase ^ (1 << 13)) >> 2) + qg];

                // chain A: self + bits 0,1 (register permutes)
                uint64_t s01 = pack2(s.x, s.y), s23 = pack2(s.z, s.w);
                uint64_t a01 = mul2(ws2, s01);
                uint64_t a23 = mul2(ws2, s23);
                a01 = fma2(wb2[0], pack2(s.y, s.x), a01);
                a23 = fma2(wb2[0], pack2(s.w, s.z), a23);
                a01 = fma2(wb2[1], s23, a01);
                a23 = fma2(wb2[1], s01, a23);

                // chain B: bits 2..8 from bf16 tile (independent of chain A)
                uint64_t b01, b23;
                {
                    uint2 n = *(const uint2*)(row + (qg ^ 1) * 2);
                    b01 = mul2(wb2[2], bfp_to_f32x2(n.x));
                    b23 = mul2(wb2[2], bfp_to_f32x2(n.y));
                }
                #pragma unroll
                for (int k = 3; k <= 8; ++k) {
                    int qn = qg ^ (1 << (k - 2));
                    uint2 n = *(const uint2*)(row + qn * 2);
                    b01 = fma2(wb2[k], bfp_to_f32x2(n.x), b01);
                    b23 = fma2(wb2[k], bfp_to_f32x2(n.y), b23);
                }

                // chain A continues with remote f32 quads
                a01 = fma2(wb2[ 9], pack2(g9.x,  g9.y),  a01);
                a23 = fma2(wb2[ 9], pack2(g9.z,  g9.w),  a23);
                a01 = fma2(wb2[10], pack2(g10.x, g10.y), a01);
                a23 = fma2(wb2[10], pack2(g10.z, g10.w), a23);
                a01 = fma2(wb2[11], pack2(g11.x, g11.y), a01);
                a23 = fma2(wb2[11], pack2(g11.z, g11.w), a23);
                a01 = fma2(wb2[12], pack2(g12.x, g12.y), a01);
                a23 = fma2(wb2[12], pack2(g12.z, g12.w), a23);
                a01 = fma2(wb2[13], pack2(g13.x, g13.y), a01);
                a23 = fma2(wb2[13], pack2(g13.z, g13.w), a23);

                a01 = add2(a01, b01);
                a23 = add2(a23, b23);

                float y0, y1, y2, y3;
                unpack2(a01, y0, y1);
                unpack2(a23, y2, y3);
                *(float4*)(ybuf + c * CHUNK_L + ql * 4) = make_float4(y0, y1, y2, y3);
            }
            __syncthreads();    // chunk ck ready; consumer finished ck-1
        }
    } else {
        // ---------------- consumer: mix chunks 0..3 (lagging by 1) ----------------
        const int tl = tid - 128;
        uint64_t* outp = (uint64_t*)out + (size_t)b * COUT * (LPOW / 2) + (lbase >> 1);
        for (int ck = 0; ck < NCHUNK; ++ck) {
            __syncthreads();    // wait for producer chunk ck
            const uint64_t* ybuf = (const uint64_t*)(sh_y + (ck & 1) * CIN * CHUNK_L);
            mix_chunk(ybuf, sh_w, sh_b, outp + ck * CPAIRS, tl);
        }
    }
}

extern "C" void kernel_launch(void* const* d_in, const int* in_sizes, int n_in,
                              void* d_out, int out_size)
{
    const float* x      = (const float*)d_in[0];
    const float* w_self = (const float*)d_in[1];
    const float* w_bits = (const float*)d_in[2];
    const float* mix_w  = (const float*)d_in[3];
    const float* mix_b  = (const float*)d_in[4];
    float* out = (float*)d_out;

    cudaFuncSetAttribute(hamming_kernel,
                         cudaFuncAttributeMaxDynamicSharedMemorySize, SMEM_TOTAL);

    dim3 grid(LPOW / TILE_L, 32, 1);   // (32 tiles, 32 batches) = 1024 blocks
    hamming_kernel<<<grid, TPB, SMEM_TOTAL>>>(x, w_self, w_bits, mix_w, mix_b, out);
}